// round 16
// baseline (speedup 1.0000x reference)
#include <cuda_runtime.h>
#include <cuda_bf16.h>
#include <math.h>
#include <stdint.h>

#define FULL_MASK 0xffffffffu

#define BATCH   32
#define DIM     4096
#define NQ      32
#define NKV     8
#define HD      128
#define QKV_N   6144
#define REP     4
#define KSPLIT  8
#define KLEN    (DIM / KSPLIT)   // 512
#define TSPLIT  16
#define CHUNK_MAX 128            // ceil(2048 / TSPLIT)

// Scratch (device globals; no allocation allowed)
__device__ float g_qkv[BATCH * QKV_N];                    // post-reduce, post-RoPE
__device__ float g_att[BATCH * DIM];                      // attention output, pre-wo
__device__ float g_part_qkv[KSPLIT][BATCH][QKV_N];        // split-K partials
__device__ float g_part_o[KSPLIT][BATCH][DIM];
__device__ float g_attp[TSPLIT][BATCH][NKV][REP][HD];     // split-T partial A*V (unnormalized)
__device__ float g_attm[TSPLIT][BATCH][NKV][REP];         // split-T local max
__device__ float g_atts[TSPLIT][BATCH][NKV][REP];         // split-T local expsum

// ---------------- helpers ----------------
__device__ __forceinline__ uint32_t f2tf(float x) {
    uint32_t r; asm("cvt.rna.tf32.f32 %0, %1;" : "=r"(r) : "f"(x)); return r;
}

#define MMA_TF32(D, A0, A1, A2, A3, B0, B1)                                  \
    asm volatile(                                                            \
        "mma.sync.aligned.m16n8k8.row.col.f32.tf32.tf32.f32 "               \
        "{%0,%1,%2,%3}, {%4,%5,%6,%7}, {%8,%9}, {%0,%1,%2,%3};\n"           \
        : "+f"((D)[0]), "+f"((D)[1]), "+f"((D)[2]), "+f"((D)[3])             \
        : "r"(A0), "r"(A1), "r"(A2), "r"(A3), "r"(B0), "r"(B1))

// ---------------- QKV projection: 3xTF32 mma.sync (m16n8k8) ----------------
// Block: 128 threads (4 warps). M = 32, N-tile = 64, K-slice = KLEN.
// hi/lo split recovers ~fp32 precision (errors feed softmax — must stay tight).
__global__ void gemm_qkv_kernel(const float* __restrict__ x,
                                const float* __restrict__ wq,
                                const float* __restrict__ wk,
                                const float* __restrict__ wv)
{
    const int n0   = blockIdx.x * 64;
    const int kbeg = blockIdx.y * KLEN;
    const float* W;
    int wrow0;
    if (n0 < 4096)      { W = wq; wrow0 = n0; }
    else if (n0 < 5120) { W = wk; wrow0 = n0 - 4096; }
    else                { W = wv; wrow0 = n0 - 5120; }
    float* C = &g_part_qkv[blockIdx.y][0][0];        // ldc = QKV_N

    __shared__ __align__(16) uint32_t Ah[32][36], Al[32][36];
    __shared__ __align__(16) uint32_t Bh[64][36], Bl[64][36];

    const int tid  = threadIdx.x;
    const int wid  = tid >> 5;       // 0..3
    const int lane = tid & 31;
    const int gid  = lane >> 2;      // 0..7
    const int tg   = lane & 3;       // 0..3

    float d[2][2][4];
#pragma unroll
    for (int mt = 0; mt < 2; mt++)
#pragma unroll
        for (int nt = 0; nt < 2; nt++)
#pragma unroll
            for (int i = 0; i < 4; i++) d[mt][nt][i] = 0.f;

    for (int k0 = kbeg; k0 < kbeg + KLEN; k0 += 32) {
        // A tile: 32 rows x 32 k; hi/lo tf32 split
#pragma unroll
        for (int j = 0; j < 2; j++) {
            int e  = tid + j * 128;
            int m  = e >> 3;
            int kk = (e & 7) * 4;
            float4 v = *reinterpret_cast<const float4*>(&x[(size_t)m * DIM + k0 + kk]);
            uint4 h = make_uint4(f2tf(v.x), f2tf(v.y), f2tf(v.z), f2tf(v.w));
            uint4 l = make_uint4(f2tf(v.x - __uint_as_float(h.x)),
                                 f2tf(v.y - __uint_as_float(h.y)),
                                 f2tf(v.z - __uint_as_float(h.z)),
                                 f2tf(v.w - __uint_as_float(h.w)));
            *reinterpret_cast<uint4*>(&Ah[m][kk]) = h;
            *reinterpret_cast<uint4*>(&Al[m][kk]) = l;
        }
        // B tile: 64 n-rows x 32 k; hi/lo tf32 split
#pragma unroll
        for (int j = 0; j < 4; j++) {
            int e  = tid + j * 128;
            int n  = e >> 3;
            int kk = (e & 7) * 4;
            float4 v = *reinterpret_cast<const float4*>(&W[(size_t)(wrow0 + n) * DIM + k0 + kk]);
            uint4 h = make_uint4(f2tf(v.x), f2tf(v.y), f2tf(v.z), f2tf(v.w));
            uint4 l = make_uint4(f2tf(v.x - __uint_as_float(h.x)),
                                 f2tf(v.y - __uint_as_float(h.y)),
                                 f2tf(v.z - __uint_as_float(h.z)),
                                 f2tf(v.w - __uint_as_float(h.w)));
            *reinterpret_cast<uint4*>(&Bh[n][kk]) = h;
            *reinterpret_cast<uint4*>(&Bl[n][kk]) = l;
        }
        __syncthreads();

#pragma unroll
        for (int ks = 0; ks < 4; ks++) {
            const int kb = ks * 8;
            uint32_t ah[2][4], al[2][4], bh[2][2], bl[2][2];
#pragma unroll
            for (int mt = 0; mt < 2; mt++) {
                int r0 = gid + mt * 16, r1 = gid + 8 + mt * 16;
                ah[mt][0] = Ah[r0][kb + tg];     ah[mt][1] = Ah[r1][kb + tg];
                ah[mt][2] = Ah[r0][kb + tg + 4]; ah[mt][3] = Ah[r1][kb + tg + 4];
                al[mt][0] = Al[r0][kb + tg];     al[mt][1] = Al[r1][kb + tg];
                al[mt][2] = Al[r0][kb + tg + 4]; al[mt][3] = Al[r1][kb + tg + 4];
            }
#pragma unroll
            for (int nt = 0; nt < 2; nt++) {
                int nc = wid * 16 + nt * 8 + gid;
                bh[nt][0] = Bh[nc][kb + tg]; bh[nt][1] = Bh[nc][kb + tg + 4];
                bl[nt][0] = Bl[nc][kb + tg]; bl[nt][1] = Bl[nc][kb + tg + 4];
            }
#pragma unroll
            for (int mt = 0; mt < 2; mt++)
#pragma unroll
                for (int nt = 0; nt < 2; nt++) {
                    // small terms first, then hi*hi
                    MMA_TF32(d[mt][nt], al[mt][0], al[mt][1], al[mt][2], al[mt][3],
                             bh[nt][0], bh[nt][1]);
                    MMA_TF32(d[mt][nt], ah[mt][0], ah[mt][1], ah[mt][2], ah[mt][3],
                             bl[nt][0], bl[nt][1]);
                    MMA_TF32(d[mt][nt], ah[mt][0], ah[mt][1], ah[mt][2], ah[mt][3],
                             bh[nt][0], bh[nt][1]);
                }
        }
        __syncthreads();
    }

#pragma unroll
    for (int mt = 0; mt < 2; mt++)
#pragma unroll
        for (int nt = 0; nt < 2; nt++) {
            int col = n0 + wid * 16 + nt * 8 + 2 * tg;
            int r0  = gid + mt * 16;
            *reinterpret_cast<float2*>(&C[(size_t)r0 * QKV_N + col]) =
                make_float2(d[mt][nt][0], d[mt][nt][1]);
            *reinterpret_cast<float2*>(&C[(size_t)(r0 + 8) * QKV_N + col]) =
                make_float2(d[mt][nt][2], d[mt][nt][3]);
        }
}

// ---------------- Output projection: tf32 mma.sync (m16n8k8) — proven ----------------
__global__ void gemm_o_kernel(const float* __restrict__ wo)
{
    const int n0   = blockIdx.x * 64;
    const int kbeg = blockIdx.y * KLEN;
    const float* A = g_att;                          // [32][DIM]
    float* C = &g_part_o[blockIdx.y][0][0];          // ldc = DIM

    __shared__ __align__(16) uint32_t As2[32][36];   // A, m-major, tf32 bits
    __shared__ __align__(16) uint32_t Bs[64][36];    // W, n-major, tf32 bits

    const int tid  = threadIdx.x;
    const int wid  = tid >> 5;       // 0..3
    const int lane = tid & 31;
    const int gid  = lane >> 2;      // 0..7
    const int tg   = lane & 3;       // 0..3

    float d[2][2][4];
#pragma unroll
    for (int mt = 0; mt < 2; mt++)
#pragma unroll
        for (int nt = 0; nt < 2; nt++)
#pragma unroll
            for (int i = 0; i < 4; i++) d[mt][nt][i] = 0.f;

    for (int k0 = kbeg; k0 < kbeg + KLEN; k0 += 32) {
#pragma unroll
        for (int j = 0; j < 2; j++) {
            int e  = tid + j * 128;
            int m  = e >> 3;
            int kk = (e & 7) * 4;
            float4 v = *reinterpret_cast<const float4*>(&A[(size_t)m * DIM + k0 + kk]);
            uint4 u = make_uint4(f2tf(v.x), f2tf(v.y), f2tf(v.z), f2tf(v.w));
            *reinterpret_cast<uint4*>(&As2[m][kk]) = u;
        }
#pragma unroll
        for (int j = 0; j < 4; j++) {
            int e  = tid + j * 128;
            int n  = e >> 3;
            int kk = (e & 7) * 4;
            float4 v = *reinterpret_cast<const float4*>(&wo[(size_t)(n0 + n) * DIM + k0 + kk]);
            uint4 u = make_uint4(f2tf(v.x), f2tf(v.y), f2tf(v.z), f2tf(v.w));
            *reinterpret_cast<uint4*>(&Bs[n][kk]) = u;
        }
        __syncthreads();

#pragma unroll
        for (int ks = 0; ks < 4; ks++) {
            const int kb = ks * 8;
            uint32_t a[2][4], bf[2][2];
#pragma unroll
            for (int mt = 0; mt < 2; mt++) {
                a[mt][0] = As2[gid +     mt * 16][kb + tg];
                a[mt][1] = As2[gid + 8 + mt * 16][kb + tg];
                a[mt][2] = As2[gid +     mt * 16][kb + tg + 4];
                a[mt][3] = As2[gid + 8 + mt * 16][kb + tg + 4];
            }
#pragma unroll
            for (int nt = 0; nt < 2; nt++) {
                int nc = wid * 16 + nt * 8 + gid;
                bf[nt][0] = Bs[nc][kb + tg];
                bf[nt][1] = Bs[nc][kb + tg + 4];
            }
#pragma unroll
            for (int mt = 0; mt < 2; mt++)
#pragma unroll
                for (int nt = 0; nt < 2; nt++)
                    MMA_TF32(d[mt][nt], a[mt][0], a[mt][1], a[mt][2], a[mt][3],
                             bf[nt][0], bf[nt][1]);
        }
        __syncthreads();
    }

#pragma unroll
    for (int mt = 0; mt < 2; mt++)
#pragma unroll
        for (int nt = 0; nt < 2; nt++) {
            int col = n0 + wid * 16 + nt * 8 + 2 * tg;
            int r0  = gid + mt * 16;
            *reinterpret_cast<float2*>(&C[(size_t)r0 * DIM + col]) =
                make_float2(d[mt][nt][0], d[mt][nt][1]);
            *reinterpret_cast<float2*>(&C[(size_t)(r0 + 8) * DIM + col]) =
                make_float2(d[mt][nt][2], d[mt][nt][3]);
        }
}

// ---------------- QKV reduce + fused RoPE ----------------
__global__ void reduce_qkv_rope(const float* __restrict__ cosv,
                                const float* __restrict__ sinv)
{
    int idx = blockIdx.x * 256 + threadIdx.x;
    if (idx >= BATCH * (QKV_N / 2)) return;
    int b  = idx / (QKV_N / 2);
    int pr = idx - b * (QKV_N / 2);
    int col = pr * 2;

    float sx = 0.f, sy = 0.f;
#pragma unroll
    for (int ks = 0; ks < KSPLIT; ks++) {
        float2 v = *reinterpret_cast<const float2*>(&g_part_qkv[ks][b][col]);
        sx += v.x; sy += v.y;
    }
    float2 o;
    if (col < 5120) {
        int d2 = (col & (HD - 1)) >> 1;
        float c = cosv[d2], s = sinv[d2];
        o.x = sx * c - sy * s;
        o.y = sx * s + sy * c;
    } else {
        o.x = sx; o.y = sy;
    }
    *reinterpret_cast<float2*>(&g_qkv[(size_t)b * QKV_N + col]) = o;
}

__global__ void reduce_o(float* __restrict__ out)
{
    int idx = blockIdx.x * 256 + threadIdx.x;
    if (idx >= BATCH * (DIM / 2)) return;
    int b  = idx / (DIM / 2);
    int pr = idx - b * (DIM / 2);
    int col = pr * 2;
    float sx = 0.f, sy = 0.f;
#pragma unroll
    for (int ks = 0; ks < KSPLIT; ks++) {
        float2 v = *reinterpret_cast<const float2*>(&g_part_o[ks][b][col]);
        sx += v.x; sy += v.y;
    }
    *reinterpret_cast<float2*>(&out[(size_t)b * DIM + col]) = make_float2(sx, sy);
}

// ---------------- Attention partials: grid (NKV, BATCH, TSPLIT), 512 thr ----------------
__global__ void __launch_bounds__(512, 2)
attn_part_kernel(const float* __restrict__ cache_k,
                 const float* __restrict__ cache_v,
                 const int* __restrict__ sp_ptr,
                 int max_seq)
{
    const int g    = blockIdx.x;
    const int b    = blockIdx.y;
    const int ts   = blockIdx.z;
    const int tid  = threadIdx.x;     // 0..511
    const int lane = tid & 31;
    const int w    = tid >> 5;        // 0..15
    const int sp   = *sp_ptr;
    const int T    = sp + 1;
    const int chunk = (T + TSPLIT - 1) / TSPLIT;
    const int t0   = ts * chunk;
    const int t1   = min(t0 + chunk, T);

    // output mapping (r, d) for zero-fill / final stores
    const int dv = tid & (HD - 1);    // 0..127
    const int tq = tid >> 7;          // 0..3

    if (t0 >= T) {     // empty split
        if (tid < REP) { g_attm[ts][b][g][tid] = -3.0e38f; g_atts[ts][b][g][tid] = 0.f; }
        if (tq == 0)
#pragma unroll
            for (int r = 0; r < REP; r++) g_attp[ts][b][g][r][dv] = 0.f;
        return;
    }
    const int n = t1 - t0;            // <= CHUNK_MAX

    __shared__ float sc[REP][CHUNK_MAX];
    __shared__ float q4s[REP][HD];
    __shared__ float redm[REP][4];
    __shared__ float reds[REP][4];
    __shared__ float rmax[REP];
    __shared__ float rsum[REP];
    __shared__ __align__(16) float vred16[16][REP][HD];   // 32KB cross-warp V reduction

    for (int i = tid; i < REP * HD; i += 512) {
        int rr = i >> 7, dd = i & (HD - 1);
        q4s[rr][dd] = g_qkv[(size_t)b * QKV_N + (g * REP + rr) * HD + dd];
    }
    __syncthreads();

    float4 q0 = reinterpret_cast<const float4*>(q4s[0])[lane];
    float4 q1 = reinterpret_cast<const float4*>(q4s[1])[lane];
    float4 q2 = reinterpret_cast<const float4*>(q4s[2])[lane];
    float4 q3 = reinterpret_cast<const float4*>(q4s[3])[lane];

    const float* knew = &g_qkv[(size_t)b * QKV_N + 4096 + g * HD];
    const float* vnew = &g_qkv[(size_t)b * QKV_N + 5120 + g * HD];
    const float scale = 0.08838834764831845f;   // 1/sqrt(128)

    // ---- scores: warp-per-t, 2-stage prefetch + 6-shuffle reduction (proven) ----
    {
        int t = t0 + w;
        float4 kc;
        if (t < t1) {
            const float* kp = (t < sp)
                ? &cache_k[(((size_t)b * max_seq + t) * NKV + g) * HD]
                : knew;
            kc = reinterpret_cast<const float4*>(kp)[lane];
        }
        for (; t < t1; t += 16) {
            // prefetch next t for this warp
            const int tn = t + 16;
            float4 kn;
            if (tn < t1) {
                const float* kp2 = (tn < sp)
                    ? &cache_k[(((size_t)b * max_seq + tn) * NKV + g) * HD]
                    : knew;
                kn = reinterpret_cast<const float4*>(kp2)[lane];
            }

            float p0 = q0.x*kc.x + q0.y*kc.y + q0.z*kc.z + q0.w*kc.w;
            float p1 = q1.x*kc.x + q1.y*kc.y + q1.z*kc.z + q1.w*kc.w;
            float p2 = q2.x*kc.x + q2.y*kc.y + q2.z*kc.z + q2.w*kc.w;
            float p3 = q3.x*kc.x + q3.y*kc.y + q3.z*kc.z + q3.w*kc.w;

            // round 16: route p0/p1 and p2/p3 into half-warps
            float x01 = (lane & 16) ? p1 : p0;
            float z01 = (lane & 16) ? p0 : p1;
            float s01 = x01 + __shfl_xor_sync(FULL_MASK, z01, 16);
            float x23 = (lane & 16) ? p3 : p2;
            float z23 = (lane & 16) ? p2 : p3;
            float s23 = x23 + __shfl_xor_sync(FULL_MASK, z23, 16);
            // round 8: route into 8-lane groups (0-7:p0, 8-15:p2, 16-23:p1, 24-31:p3)
            float xx = (lane & 8) ? s23 : s01;
            float zz = (lane & 8) ? s01 : s23;
            float v  = xx + __shfl_xor_sync(FULL_MASK, zz, 8);
            // rounds 4,2,1 within 8-lane groups
            v += __shfl_xor_sync(FULL_MASK, v, 4);
            v += __shfl_xor_sync(FULL_MASK, v, 2);
            v += __shfl_xor_sync(FULL_MASK, v, 1);

            if ((lane & 7) == 0) {
                int r = ((lane >> 4) & 1) | (((lane >> 3) & 1) << 1);  // 0->0, 8->2, 16->1, 24->3
                sc[r][t - t0] = v * scale;
            }
            kc = kn;
        }
    }
    __syncthreads();

    // ---- local softmax: all 4 reps in parallel (128 threads per rep) ----
    {
        const int rr  = tid >> 7;
        const int tt  = tid & 127;
        const int wq4 = (tid >> 5) & 3;

        float mv = (tt < n) ? sc[rr][tt] : -3.0e38f;
#pragma unroll
        for (int off = 16; off; off >>= 1) mv = fmaxf(mv, __shfl_xor_sync(FULL_MASK, mv, off));
        if (lane == 0) redm[rr][wq4] = mv;
        __syncthreads();
        float m = fmaxf(fmaxf(redm[rr][0], redm[rr][1]),
                        fmaxf(redm[rr][2], redm[rr][3]));

        float e = 0.f;
        if (tt < n) {
            e = __expf(sc[rr][tt] - m);
            sc[rr][tt] = e;
        }
        float s = e;
#pragma unroll
        for (int off = 16; off; off >>= 1) s += __shfl_xor_sync(FULL_MASK, s, off);
        if (lane == 0) reds[rr][wq4] = s;
        __syncthreads();
        if (tt == 0) {
            rmax[rr] = m;
            rsum[rr] = reds[rr][0] + reds[rr][1] + reds[rr][2] + reds[rr][3];
        }
    }
    __syncthreads();

    // ---- partial A @ V: warp-per-t, float4 per lane (LDG.128), 4 reps in regs ----
    {
        float4 a0 = make_float4(0.f, 0.f, 0.f, 0.f);
        float4 a1 = make_float4(0.f, 0.f, 0.f, 0.f);
        float4 a2 = make_float4(0.f, 0.f, 0.f, 0.f);
        float4 a3 = make_float4(0.f, 0.f, 0.f, 0.f);
#pragma unroll 4
        for (int t = t0 + w; t < t1; t += 16) {
            const float* vp = (t < sp)
                ? &cache_v[(((size_t)b * max_seq + t) * NKV + g) * HD]
                : vnew;
            float4 v = reinterpret_cast<const float4*>(vp)[lane];
            int tt = t - t0;
            float s0 = sc[0][tt], s1 = sc[1][tt], s2 = sc[2][tt], s3 = sc[3][tt];
            a0.x += s0 * v.x; a0.y += s0 * v.y; a0.z += s0 * v.z; a0.w += s0 * v.w;
            a1.x += s1 * v.x; a1.y += s1 * v.y; a1.z += s1 * v.z; a1.w += s1 * v.w;
            a2.x += s2 * v.x; a2.y += s2 * v.y; a2.z += s2 * v.z; a2.w += s2 * v.w;
            a3.x += s3 * v.x; a3.y += s3 * v.y; a3.z += s3 * v.z; a3.w += s3 * v.w;
        }
        *reinterpret_cast<float4*>(&vred16[w][0][lane * 4]) = a0;
        *reinterpret_cast<float4*>(&vred16[w][1][lane * 4]) = a1;
        *reinterpret_cast<float4*>(&vred16[w][2][lane * 4]) = a2;
        *reinterpret_cast<float4*>(&vred16[w][3][lane * 4]) = a3;
    }
    __syncthreads();

    // ---- cross-warp reduce: thread (tq=r, dv) sums 16 partials ----
    {
        float s = 0.f;
#pragma unroll
        for (int ww = 0; ww < 16; ww++) s += vred16[ww][tq][dv];
        g_attp[ts][b][g][tq][dv] = s;
    }
    if (tid < REP) {
        g_attm[ts][b][g][tid] = rmax[tid];
        g_atts[ts][b][g][tid] = rsum[tid];
    }
}

// ---------------- Attention combine: grid (NKV, BATCH), 512 thr ----------------
__global__ void attn_combine_kernel()
{
    const int g   = blockIdx.x;
    const int b   = blockIdx.y;
    const int tid = threadIdx.x;
    const int d   = tid & (HD - 1);
    const int r   = tid >> 7;

    float M = -3.0e38f;
#pragma unroll
    for (int ts = 0; ts < TSPLIT; ts++) M = fmaxf(M, g_attm[ts][b][g][r]);

    float S = 0.f, a = 0.f;
#pragma unroll
    for (int ts = 0; ts < TSPLIT; ts++) {
        float f = __expf(g_attm[ts][b][g][r] - M);
        S += g_atts[ts][b][g][r] * f;
        a += g_attp[ts][b][g][r][d] * f;
    }
    g_att[(size_t)b * DIM + (g * REP + r) * HD + d] = a / S;
}

// ---------------- launch ----------------
extern "C" void kernel_launch(void* const* d_in, const int* in_sizes, int n_in,
                              void* d_out, int out_size)
{
    const float* x  = (const float*)d_in[0];
    const float* wq = (const float*)d_in[1];
    const float* wk = (const float*)d_in[2];
    const float* wv = (const float*)d_in[3];
    const float* wo = (const float*)d_in[4];
    const float* fc = (const float*)d_in[5];
    const float* fs = (const float*)d_in[6];
    const float* ck = (const float*)d_in[7];
    const float* cv = (const float*)d_in[8];
    const int*   sp = (const int*)d_in[9];

    int max_seq = in_sizes[7] / (BATCH * NKV * HD);

    gemm_qkv_kernel<<<dim3(QKV_N / 64, KSPLIT), 128>>>(x, wq, wk, wv);
    reduce_qkv_rope<<<(BATCH * (QKV_N / 2) + 255) / 256, 256>>>(fc, fs);
    attn_part_kernel<<<dim3(NKV, BATCH, TSPLIT), 512>>>(ck, cv, sp, max_seq);
    attn_combine_kernel<<<dim3(NKV, BATCH), 512>>>();
    gemm_o_kernel<<<dim3(DIM / 64, KSPLIT), 128>>>(wo);
    reduce_o<<<(BATCH * (DIM / 2) + 255) / 256, 256>>>((float*)d_out);
}

// round 17
// speedup vs baseline: 1.0786x; 1.0786x over previous
#include <cuda_runtime.h>
#include <cuda_bf16.h>
#include <math.h>
#include <stdint.h>

#define FULL_MASK 0xffffffffu

#define BATCH   32
#define DIM     4096
#define NQ      32
#define NKV     8
#define HD      128
#define QKV_N   6144
#define REP     4
#define KSPLIT  16
#define KLEN    (DIM / KSPLIT)   // 256
#define TSPLIT  16
#define CHUNK_MAX 128            // ceil(2048 / TSPLIT)

// Scratch (device globals; no allocation allowed)
__device__ float g_qkv[BATCH * QKV_N];                    // post-reduce, post-RoPE
__device__ float g_att[BATCH * DIM];                      // attention output, pre-wo
__device__ float g_part_qkv[KSPLIT][BATCH][QKV_N];        // split-K partials
__device__ float g_part_o[KSPLIT][BATCH][DIM];
__device__ float g_attp[TSPLIT][BATCH][NKV][REP][HD];     // split-T partial A*V (unnormalized)
__device__ float g_attm[TSPLIT][BATCH][NKV][REP];         // split-T local max
__device__ float g_atts[TSPLIT][BATCH][NKV][REP];         // split-T local expsum

// ---------------- helpers ----------------
__device__ __forceinline__ uint32_t f2tf(float x) {
    uint32_t r; asm("cvt.rna.tf32.f32 %0, %1;" : "=r"(r) : "f"(x)); return r;
}

#define MMA_TF32(D, A0, A1, A2, A3, B0, B1)                                  \
    asm volatile(                                                            \
        "mma.sync.aligned.m16n8k8.row.col.f32.tf32.tf32.f32 "               \
        "{%0,%1,%2,%3}, {%4,%5,%6,%7}, {%8,%9}, {%0,%1,%2,%3};\n"           \
        : "+f"((D)[0]), "+f"((D)[1]), "+f"((D)[2]), "+f"((D)[3])             \
        : "r"(A0), "r"(A1), "r"(A2), "r"(A3), "r"(B0), "r"(B1))

// ---------------- QKV projection: 3xTF32 mma.sync (m16n8k8) ----------------
// Block: 128 threads (4 warps). M = 32, N-tile = 64, K-slice = KLEN.
// hi/lo split recovers ~fp32 precision (errors feed softmax — must stay tight).
__global__ void gemm_qkv_kernel(const float* __restrict__ x,
                                const float* __restrict__ wq,
                                const float* __restrict__ wk,
                                const float* __restrict__ wv)
{
    const int n0   = blockIdx.x * 64;
    const int kbeg = blockIdx.y * KLEN;
    const float* W;
    int wrow0;
    if (n0 < 4096)      { W = wq; wrow0 = n0; }
    else if (n0 < 5120) { W = wk; wrow0 = n0 - 4096; }
    else                { W = wv; wrow0 = n0 - 5120; }
    float* C = &g_part_qkv[blockIdx.y][0][0];        // ldc = QKV_N

    __shared__ __align__(16) uint32_t Ah[32][36], Al[32][36];
    __shared__ __align__(16) uint32_t Bh[64][36], Bl[64][36];

    const int tid  = threadIdx.x;
    const int wid  = tid >> 5;       // 0..3
    const int lane = tid & 31;
    const int gid  = lane >> 2;      // 0..7
    const int tg   = lane & 3;       // 0..3

    float d[2][2][4];
#pragma unroll
    for (int mt = 0; mt < 2; mt++)
#pragma unroll
        for (int nt = 0; nt < 2; nt++)
#pragma unroll
            for (int i = 0; i < 4; i++) d[mt][nt][i] = 0.f;

    for (int k0 = kbeg; k0 < kbeg + KLEN; k0 += 32) {
        // A tile: 32 rows x 32 k; hi/lo tf32 split
#pragma unroll
        for (int j = 0; j < 2; j++) {
            int e  = tid + j * 128;
            int m  = e >> 3;
            int kk = (e & 7) * 4;
            float4 v = *reinterpret_cast<const float4*>(&x[(size_t)m * DIM + k0 + kk]);
            uint4 h = make_uint4(f2tf(v.x), f2tf(v.y), f2tf(v.z), f2tf(v.w));
            uint4 l = make_uint4(f2tf(v.x - __uint_as_float(h.x)),
                                 f2tf(v.y - __uint_as_float(h.y)),
                                 f2tf(v.z - __uint_as_float(h.z)),
                                 f2tf(v.w - __uint_as_float(h.w)));
            *reinterpret_cast<uint4*>(&Ah[m][kk]) = h;
            *reinterpret_cast<uint4*>(&Al[m][kk]) = l;
        }
        // B tile: 64 n-rows x 32 k; hi/lo tf32 split
#pragma unroll
        for (int j = 0; j < 4; j++) {
            int e  = tid + j * 128;
            int n  = e >> 3;
            int kk = (e & 7) * 4;
            float4 v = *reinterpret_cast<const float4*>(&W[(size_t)(wrow0 + n) * DIM + k0 + kk]);
            uint4 h = make_uint4(f2tf(v.x), f2tf(v.y), f2tf(v.z), f2tf(v.w));
            uint4 l = make_uint4(f2tf(v.x - __uint_as_float(h.x)),
                                 f2tf(v.y - __uint_as_float(h.y)),
                                 f2tf(v.z - __uint_as_float(h.z)),
                                 f2tf(v.w - __uint_as_float(h.w)));
            *reinterpret_cast<uint4*>(&Bh[n][kk]) = h;
            *reinterpret_cast<uint4*>(&Bl[n][kk]) = l;
        }
        __syncthreads();

#pragma unroll
        for (int ks = 0; ks < 4; ks++) {
            const int kb = ks * 8;
            uint32_t ah[2][4], al[2][4], bh[2][2], bl[2][2];
#pragma unroll
            for (int mt = 0; mt < 2; mt++) {
                int r0 = gid + mt * 16, r1 = gid + 8 + mt * 16;
                ah[mt][0] = Ah[r0][kb + tg];     ah[mt][1] = Ah[r1][kb + tg];
                ah[mt][2] = Ah[r0][kb + tg + 4]; ah[mt][3] = Ah[r1][kb + tg + 4];
                al[mt][0] = Al[r0][kb + tg];     al[mt][1] = Al[r1][kb + tg];
                al[mt][2] = Al[r0][kb + tg + 4]; al[mt][3] = Al[r1][kb + tg + 4];
            }
#pragma unroll
            for (int nt = 0; nt < 2; nt++) {
                int nc = wid * 16 + nt * 8 + gid;
                bh[nt][0] = Bh[nc][kb + tg]; bh[nt][1] = Bh[nc][kb + tg + 4];
                bl[nt][0] = Bl[nc][kb + tg]; bl[nt][1] = Bl[nc][kb + tg + 4];
            }
#pragma unroll
            for (int mt = 0; mt < 2; mt++)
#pragma unroll
                for (int nt = 0; nt < 2; nt++) {
                    // small terms first, then hi*hi
                    MMA_TF32(d[mt][nt], al[mt][0], al[mt][1], al[mt][2], al[mt][3],
                             bh[nt][0], bh[nt][1]);
                    MMA_TF32(d[mt][nt], ah[mt][0], ah[mt][1], ah[mt][2], ah[mt][3],
                             bl[nt][0], bl[nt][1]);
                    MMA_TF32(d[mt][nt], ah[mt][0], ah[mt][1], ah[mt][2], ah[mt][3],
                             bh[nt][0], bh[nt][1]);
                }
        }
        __syncthreads();
    }

#pragma unroll
    for (int mt = 0; mt < 2; mt++)
#pragma unroll
        for (int nt = 0; nt < 2; nt++) {
            int col = n0 + wid * 16 + nt * 8 + 2 * tg;
            int r0  = gid + mt * 16;
            *reinterpret_cast<float2*>(&C[(size_t)r0 * QKV_N + col]) =
                make_float2(d[mt][nt][0], d[mt][nt][1]);
            *reinterpret_cast<float2*>(&C[(size_t)(r0 + 8) * QKV_N + col]) =
                make_float2(d[mt][nt][2], d[mt][nt][3]);
        }
}

// ---------------- Output projection: tf32 mma.sync (m16n8k8) — proven ----------------
__global__ void gemm_o_kernel(const float* __restrict__ wo)
{
    const int n0   = blockIdx.x * 64;
    const int kbeg = blockIdx.y * KLEN;
    const float* A = g_att;                          // [32][DIM]
    float* C = &g_part_o[blockIdx.y][0][0];          // ldc = DIM

    __shared__ __align__(16) uint32_t As2[32][36];   // A, m-major, tf32 bits
    __shared__ __align__(16) uint32_t Bs[64][36];    // W, n-major, tf32 bits

    const int tid  = threadIdx.x;
    const int wid  = tid >> 5;       // 0..3
    const int lane = tid & 31;
    const int gid  = lane >> 2;      // 0..7
    const int tg   = lane & 3;       // 0..3

    float d[2][2][4];
#pragma unroll
    for (int mt = 0; mt < 2; mt++)
#pragma unroll
        for (int nt = 0; nt < 2; nt++)
#pragma unroll
            for (int i = 0; i < 4; i++) d[mt][nt][i] = 0.f;

    for (int k0 = kbeg; k0 < kbeg + KLEN; k0 += 32) {
#pragma unroll
        for (int j = 0; j < 2; j++) {
            int e  = tid + j * 128;
            int m  = e >> 3;
            int kk = (e & 7) * 4;
            float4 v = *reinterpret_cast<const float4*>(&A[(size_t)m * DIM + k0 + kk]);
            uint4 u = make_uint4(f2tf(v.x), f2tf(v.y), f2tf(v.z), f2tf(v.w));
            *reinterpret_cast<uint4*>(&As2[m][kk]) = u;
        }
#pragma unroll
        for (int j = 0; j < 4; j++) {
            int e  = tid + j * 128;
            int n  = e >> 3;
            int kk = (e & 7) * 4;
            float4 v = *reinterpret_cast<const float4*>(&wo[(size_t)(n0 + n) * DIM + k0 + kk]);
            uint4 u = make_uint4(f2tf(v.x), f2tf(v.y), f2tf(v.z), f2tf(v.w));
            *reinterpret_cast<uint4*>(&Bs[n][kk]) = u;
        }
        __syncthreads();

#pragma unroll
        for (int ks = 0; ks < 4; ks++) {
            const int kb = ks * 8;
            uint32_t a[2][4], bf[2][2];
#pragma unroll
            for (int mt = 0; mt < 2; mt++) {
                a[mt][0] = As2[gid +     mt * 16][kb + tg];
                a[mt][1] = As2[gid + 8 + mt * 16][kb + tg];
                a[mt][2] = As2[gid +     mt * 16][kb + tg + 4];
                a[mt][3] = As2[gid + 8 + mt * 16][kb + tg + 4];
            }
#pragma unroll
            for (int nt = 0; nt < 2; nt++) {
                int nc = wid * 16 + nt * 8 + gid;
                bf[nt][0] = Bs[nc][kb + tg];
                bf[nt][1] = Bs[nc][kb + tg + 4];
            }
#pragma unroll
            for (int mt = 0; mt < 2; mt++)
#pragma unroll
                for (int nt = 0; nt < 2; nt++)
                    MMA_TF32(d[mt][nt], a[mt][0], a[mt][1], a[mt][2], a[mt][3],
                             bf[nt][0], bf[nt][1]);
        }
        __syncthreads();
    }

#pragma unroll
    for (int mt = 0; mt < 2; mt++)
#pragma unroll
        for (int nt = 0; nt < 2; nt++) {
            int col = n0 + wid * 16 + nt * 8 + 2 * tg;
            int r0  = gid + mt * 16;
            *reinterpret_cast<float2*>(&C[(size_t)r0 * DIM + col]) =
                make_float2(d[mt][nt][0], d[mt][nt][1]);
            *reinterpret_cast<float2*>(&C[(size_t)(r0 + 8) * DIM + col]) =
                make_float2(d[mt][nt][2], d[mt][nt][3]);
        }
}

// ---------------- QKV reduce + fused RoPE ----------------
__global__ void reduce_qkv_rope(const float* __restrict__ cosv,
                                const float* __restrict__ sinv)
{
    int idx = blockIdx.x * 256 + threadIdx.x;
    if (idx >= BATCH * (QKV_N / 2)) return;
    int b  = idx / (QKV_N / 2);
    int pr = idx - b * (QKV_N / 2);
    int col = pr * 2;

    float sx = 0.f, sy = 0.f;
#pragma unroll
    for (int ks = 0; ks < KSPLIT; ks++) {
        float2 v = *reinterpret_cast<const float2*>(&g_part_qkv[ks][b][col]);
        sx += v.x; sy += v.y;
    }
    float2 o;
    if (col < 5120) {
        int d2 = (col & (HD - 1)) >> 1;
        float c = cosv[d2], s = sinv[d2];
        o.x = sx * c - sy * s;
        o.y = sx * s + sy * c;
    } else {
        o.x = sx; o.y = sy;
    }
    *reinterpret_cast<float2*>(&g_qkv[(size_t)b * QKV_N + col]) = o;
}

__global__ void reduce_o(float* __restrict__ out)
{
    int idx = blockIdx.x * 256 + threadIdx.x;
    if (idx >= BATCH * (DIM / 2)) return;
    int b  = idx / (DIM / 2);
    int pr = idx - b * (DIM / 2);
    int col = pr * 2;
    float sx = 0.f, sy = 0.f;
#pragma unroll
    for (int ks = 0; ks < KSPLIT; ks++) {
        float2 v = *reinterpret_cast<const float2*>(&g_part_o[ks][b][col]);
        sx += v.x; sy += v.y;
    }
    *reinterpret_cast<float2*>(&out[(size_t)b * DIM + col]) = make_float2(sx, sy);
}

// ---------------- Attention partials: grid (NKV, BATCH, TSPLIT), 512 thr ----------------
__global__ void __launch_bounds__(512, 2)
attn_part_kernel(const float* __restrict__ cache_k,
                 const float* __restrict__ cache_v,
                 const int* __restrict__ sp_ptr,
                 int max_seq)
{
    const int g    = blockIdx.x;
    const int b    = blockIdx.y;
    const int ts   = blockIdx.z;
    const int tid  = threadIdx.x;     // 0..511
    const int lane = tid & 31;
    const int w    = tid >> 5;        // 0..15
    const int sp   = *sp_ptr;
    const int T    = sp + 1;
    const int chunk = (T + TSPLIT - 1) / TSPLIT;
    const int t0   = ts * chunk;
    const int t1   = min(t0 + chunk, T);

    // output mapping (r, d) for zero-fill / final stores
    const int dv = tid & (HD - 1);    // 0..127
    const int tq = tid >> 7;          // 0..3

    if (t0 >= T) {     // empty split
        if (tid < REP) { g_attm[ts][b][g][tid] = -3.0e38f; g_atts[ts][b][g][tid] = 0.f; }
        if (tq == 0)
#pragma unroll
            for (int r = 0; r < REP; r++) g_attp[ts][b][g][r][dv] = 0.f;
        return;
    }
    const int n = t1 - t0;            // <= CHUNK_MAX

    __shared__ float sc[REP][CHUNK_MAX];
    __shared__ float q4s[REP][HD];
    __shared__ float redm[REP][4];
    __shared__ float reds[REP][4];
    __shared__ float rmax[REP];
    __shared__ float rsum[REP];
    __shared__ __align__(16) float vred16[16][REP][HD];   // 32KB cross-warp V reduction

    for (int i = tid; i < REP * HD; i += 512) {
        int rr = i >> 7, dd = i & (HD - 1);
        q4s[rr][dd] = g_qkv[(size_t)b * QKV_N + (g * REP + rr) * HD + dd];
    }
    __syncthreads();

    float4 q0 = reinterpret_cast<const float4*>(q4s[0])[lane];
    float4 q1 = reinterpret_cast<const float4*>(q4s[1])[lane];
    float4 q2 = reinterpret_cast<const float4*>(q4s[2])[lane];
    float4 q3 = reinterpret_cast<const float4*>(q4s[3])[lane];

    const float* knew = &g_qkv[(size_t)b * QKV_N + 4096 + g * HD];
    const float* vnew = &g_qkv[(size_t)b * QKV_N + 5120 + g * HD];
    const float scale = 0.08838834764831845f;   // 1/sqrt(128)

    // ---- scores: warp-per-t, 2-stage prefetch + 6-shuffle reduction (proven) ----
    {
        int t = t0 + w;
        float4 kc;
        if (t < t1) {
            const float* kp = (t < sp)
                ? &cache_k[(((size_t)b * max_seq + t) * NKV + g) * HD]
                : knew;
            kc = reinterpret_cast<const float4*>(kp)[lane];
        }
        for (; t < t1; t += 16) {
            // prefetch next t for this warp
            const int tn = t + 16;
            float4 kn;
            if (tn < t1) {
                const float* kp2 = (tn < sp)
                    ? &cache_k[(((size_t)b * max_seq + tn) * NKV + g) * HD]
                    : knew;
                kn = reinterpret_cast<const float4*>(kp2)[lane];
            }

            float p0 = q0.x*kc.x + q0.y*kc.y + q0.z*kc.z + q0.w*kc.w;
            float p1 = q1.x*kc.x + q1.y*kc.y + q1.z*kc.z + q1.w*kc.w;
            float p2 = q2.x*kc.x + q2.y*kc.y + q2.z*kc.z + q2.w*kc.w;
            float p3 = q3.x*kc.x + q3.y*kc.y + q3.z*kc.z + q3.w*kc.w;

            // round 16: route p0/p1 and p2/p3 into half-warps
            float x01 = (lane & 16) ? p1 : p0;
            float z01 = (lane & 16) ? p0 : p1;
            float s01 = x01 + __shfl_xor_sync(FULL_MASK, z01, 16);
            float x23 = (lane & 16) ? p3 : p2;
            float z23 = (lane & 16) ? p2 : p3;
            float s23 = x23 + __shfl_xor_sync(FULL_MASK, z23, 16);
            // round 8: route into 8-lane groups (0-7:p0, 8-15:p2, 16-23:p1, 24-31:p3)
            float xx = (lane & 8) ? s23 : s01;
            float zz = (lane & 8) ? s01 : s23;
            float v  = xx + __shfl_xor_sync(FULL_MASK, zz, 8);
            // rounds 4,2,1 within 8-lane groups
            v += __shfl_xor_sync(FULL_MASK, v, 4);
            v += __shfl_xor_sync(FULL_MASK, v, 2);
            v += __shfl_xor_sync(FULL_MASK, v, 1);

            if ((lane & 7) == 0) {
                int r = ((lane >> 4) & 1) | (((lane >> 3) & 1) << 1);  // 0->0, 8->2, 16->1, 24->3
                sc[r][t - t0] = v * scale;
            }
            kc = kn;
        }
    }
    __syncthreads();

    // ---- local softmax: all 4 reps in parallel (128 threads per rep) ----
    {
        const int rr  = tid >> 7;
        const int tt  = tid & 127;
        const int wq4 = (tid >> 5) & 3;

        float mv = (tt < n) ? sc[rr][tt] : -3.0e38f;
#pragma unroll
        for (int off = 16; off; off >>= 1) mv = fmaxf(mv, __shfl_xor_sync(FULL_MASK, mv, off));
        if (lane == 0) redm[rr][wq4] = mv;
        __syncthreads();
        float m = fmaxf(fmaxf(redm[rr][0], redm[rr][1]),
                        fmaxf(redm[rr][2], redm[rr][3]));

        float e = 0.f;
        if (tt < n) {
            e = __expf(sc[rr][tt] - m);
            sc[rr][tt] = e;
        }
        float s = e;
#pragma unroll
        for (int off = 16; off; off >>= 1) s += __shfl_xor_sync(FULL_MASK, s, off);
        if (lane == 0) reds[rr][wq4] = s;
        __syncthreads();
        if (tt == 0) {
            rmax[rr] = m;
            rsum[rr] = reds[rr][0] + reds[rr][1] + reds[rr][2] + reds[rr][3];
        }
    }
    __syncthreads();

    // ---- partial A @ V: warp-per-t, float4 per lane (LDG.128), 4 reps in regs ----
    {
        float4 a0 = make_float4(0.f, 0.f, 0.f, 0.f);
        float4 a1 = make_float4(0.f, 0.f, 0.f, 0.f);
        float4 a2 = make_float4(0.f, 0.f, 0.f, 0.f);
        float4 a3 = make_float4(0.f, 0.f, 0.f, 0.f);
#pragma unroll 4
        for (int t = t0 + w; t < t1; t += 16) {
            const float* vp = (t < sp)
                ? &cache_v[(((size_t)b * max_seq + t) * NKV + g) * HD]
                : vnew;
            float4 v = reinterpret_cast<const float4*>(vp)[lane];
            int tt = t - t0;
            float s0 = sc[0][tt], s1 = sc[1][tt], s2 = sc[2][tt], s3 = sc[3][tt];
            a0.x += s0 * v.x; a0.y += s0 * v.y; a0.z += s0 * v.z; a0.w += s0 * v.w;
            a1.x += s1 * v.x; a1.y += s1 * v.y; a1.z += s1 * v.z; a1.w += s1 * v.w;
            a2.x += s2 * v.x; a2.y += s2 * v.y; a2.z += s2 * v.z; a2.w += s2 * v.w;
            a3.x += s3 * v.x; a3.y += s3 * v.y; a3.z += s3 * v.z; a3.w += s3 * v.w;
        }
        *reinterpret_cast<float4*>(&vred16[w][0][lane * 4]) = a0;
        *reinterpret_cast<float4*>(&vred16[w][1][lane * 4]) = a1;
        *reinterpret_cast<float4*>(&vred16[w][2][lane * 4]) = a2;
        *reinterpret_cast<float4*>(&vred16[w][3][lane * 4]) = a3;
    }
    __syncthreads();

    // ---- cross-warp reduce: thread (tq=r, dv) sums 16 partials ----
    {
        float s = 0.f;
#pragma unroll
        for (int ww = 0; ww < 16; ww++) s += vred16[ww][tq][dv];
        g_attp[ts][b][g][tq][dv] = s;
    }
    if (tid < REP) {
        g_attm[ts][b][g][tid] = rmax[tid];
        g_atts[ts][b][g][tid] = rsum[tid];
    }
}

// ---------------- Attention combine: grid (NKV, BATCH), 512 thr ----------------
__global__ void attn_combine_kernel()
{
    const int g   = blockIdx.x;
    const int b   = blockIdx.y;
    const int tid = threadIdx.x;
    const int d   = tid & (HD - 1);
    const int r   = tid >> 7;

    float M = -3.0e38f;
#pragma unroll
    for (int ts = 0; ts < TSPLIT; ts++) M = fmaxf(M, g_attm[ts][b][g][r]);

    float S = 0.f, a = 0.f;
#pragma unroll
    for (int ts = 0; ts < TSPLIT; ts++) {
        float f = __expf(g_attm[ts][b][g][r] - M);
        S += g_atts[ts][b][g][r] * f;
        a += g_attp[ts][b][g][r][d] * f;
    }
    g_att[(size_t)b * DIM + (g * REP + r) * HD + d] = a / S;
}

// ---------------- launch ----------------
extern "C" void kernel_launch(void* const* d_in, const int* in_sizes, int n_in,
                              void* d_out, int out_size)
{
    const float* x  = (const float*)d_in[0];
    const float* wq = (const float*)d_in[1];
    const float* wk = (const float*)d_in[2];
    const float* wv = (const float*)d_in[3];
    const float* wo = (const float*)d_in[4];
    const float* fc = (const float*)d_in[5];
    const float* fs = (const float*)d_in[6];
    const float* ck = (const float*)d_in[7];
    const float* cv = (const float*)d_in[8];
    const int*   sp = (const int*)d_in[9];

    int max_seq = in_sizes[7] / (BATCH * NKV * HD);

    gemm_qkv_kernel<<<dim3(QKV_N / 64, KSPLIT), 128>>>(x, wq, wk, wv);
    reduce_qkv_rope<<<(BATCH * (QKV_N / 2) + 255) / 256, 256>>>(fc, fs);
    attn_part_kernel<<<dim3(NKV, BATCH, TSPLIT), 512>>>(ck, cv, sp, max_seq);
    attn_combine_kernel<<<dim3(NKV, BATCH), 512>>>();
    gemm_o_kernel<<<dim3(DIM / 64, KSPLIT), 128>>>(wo);
    reduce_o<<<(BATCH * (DIM / 2) + 255) / 256, 256>>>((float*)d_out);
}